// round 1
// baseline (speedup 1.0000x reference)
#include <cuda_runtime.h>
#include <cstdint>

#define BB 8
#define NN 2048
#define KK 20

// ---------------- static scratch (no runtime allocation allowed) ----------------
__device__ float g_xt[BB * 3 * NN];
__device__ float g_xx[BB * NN];
__device__ float g_dist[(size_t)BB * NN * NN];          // 134 MB
__device__ int   g_idx[BB * NN * KK];
__device__ float g_A[(size_t)BB * 256 * NN];            // 16 MB
__device__ float g_Cc[(size_t)BB * 256 * NN];           // 16 MB
__device__ float g_xcat[(size_t)BB * 512 * NN];         // 33 MB (x1|x2|x3|x4)
__device__ float g_y5[(size_t)BB * 512 * NN];           // 33 MB
__device__ float g_sum[512];
__device__ float g_sumsq[512];
__device__ float g_scale[512];
__device__ float g_shift[512];
__device__ float g_pooled[BB * 512];

// ---------------- transpose x (B,N,3) -> (B,3,N) ----------------
__global__ void xt_kernel(const float* __restrict__ x) {
    int i = blockIdx.x * 256 + threadIdx.x;       // b*NN + n
    if (i >= BB * NN) return;
    int b = i >> 11, n = i & (NN - 1);
    #pragma unroll
    for (int c = 0; c < 3; c++)
        g_xt[(b * 3 + c) * NN + n] = x[(size_t)i * 3 + c];
}

// ---------------- squared norms per point ----------------
__global__ void xx_kernel(const float* __restrict__ Xall, int C, int bstride) {
    int i = blockIdx.x * 256 + threadIdx.x;       // b*NN + n
    int b = i >> 11, n = i & (NN - 1);
    const float* X = Xall + (size_t)b * bstride + n;
    float s = 0.f;
    for (int c = 0; c < C; c++) { float v = X[(size_t)c * NN]; s += v * v; }
    g_xx[i] = s;
}

// ---------------- distance matrix: d[n,m] = 2*inner - xx[n] - xx[m] ----------------
__global__ __launch_bounds__(256) void knn_dist_kernel(const float* __restrict__ Xall,
                                                       int C, int bstride) {
    int b = blockIdx.z;
    const float* X = Xall + (size_t)b * bstride;
    const float* xxr = g_xx + b * NN;
    float* D = g_dist + (size_t)b * NN * NN;
    int n0 = blockIdx.y * 64, m0 = blockIdx.x * 64;
    __shared__ float Ns[16][65];
    __shared__ float Ms[16][65];
    int t = threadIdx.x;
    int tn = t >> 4, tm = t & 15;
    float acc[4][4] = {};
    for (int kk = 0; kk < C; kk += 16) {
        for (int i = t; i < 16 * 64; i += 256) {
            int k = i >> 6, c = i & 63;
            float vn = 0.f, vm = 0.f;
            if (kk + k < C) {
                vn = X[(size_t)(kk + k) * NN + n0 + c];
                vm = X[(size_t)(kk + k) * NN + m0 + c];
            }
            Ns[k][c] = vn; Ms[k][c] = vm;
        }
        __syncthreads();
        #pragma unroll
        for (int k = 0; k < 16; k++) {
            float nr[4], mr[4];
            #pragma unroll
            for (int i = 0; i < 4; i++) { nr[i] = Ns[k][tn * 4 + i]; mr[i] = Ms[k][tm * 4 + i]; }
            #pragma unroll
            for (int i = 0; i < 4; i++)
                #pragma unroll
                for (int j = 0; j < 4; j++)
                    acc[i][j] += nr[i] * mr[j];
        }
        __syncthreads();
    }
    #pragma unroll
    for (int i = 0; i < 4; i++) {
        int n = n0 + tn * 4 + i;
        float xn = xxr[n];
        float4 v4;
        float* vp = &v4.x;
        #pragma unroll
        for (int j = 0; j < 4; j++) {
            int m = m0 + tm * 4 + j;
            float v = 2.0f * acc[i][j] - xn;   // diag: 2v - v = v exactly
            vp[j] = v - xxr[m];                // diag: v - v = 0 exactly
        }
        *reinterpret_cast<float4*>(&D[(size_t)n * NN + m0 + tm * 4]) = v4;
    }
}

// ---------------- top-K (K=20) per row, ties -> lowest index ----------------
__global__ __launch_bounds__(256) void topk_kernel() {
    int row = blockIdx.x;                          // b*NN + n
    const float* D = g_dist + (size_t)row * NN;
    __shared__ float sv[NN];
    __shared__ float rv[256];
    __shared__ int   ri[256];
    int t = threadIdx.x;
    for (int i = t; i < NN; i += 256) sv[i] = D[i];
    __syncthreads();
    for (int it = 0; it < KK; it++) {
        float best = -1e30f; int bi = NN;
        for (int i = t; i < NN; i += 256) {
            float v = sv[i];
            if (v > best) { best = v; bi = i; }
        }
        rv[t] = best; ri[t] = bi;
        __syncthreads();
        for (int s = 128; s > 0; s >>= 1) {
            if (t < s) {
                if (rv[t + s] > rv[t] || (rv[t + s] == rv[t] && ri[t + s] < ri[t])) {
                    rv[t] = rv[t + s]; ri[t] = ri[t + s];
                }
            }
            __syncthreads();
        }
        if (t == 0) { g_idx[(size_t)row * KK + it] = ri[0]; sv[ri[0]] = -1e30f; }
        __syncthreads();
    }
}

// ---------------- edge GEMM: A = Wl@X, Cc = (Wr-Wl)@X ----------------
__global__ __launch_bounds__(256) void edge_gemm_kernel(const float* __restrict__ W,
                                                        const float* __restrict__ Xall,
                                                        int C, int O, int bstride) {
    int b = blockIdx.z;
    const float* X = Xall + (size_t)b * bstride;
    float* Aout = g_A + (size_t)b * O * NN;
    float* Cout = g_Cc + (size_t)b * O * NN;
    int o0 = blockIdx.y * 64, n0 = blockIdx.x * 64;
    __shared__ float Xs[16][65];
    __shared__ float Wl[16][65];
    __shared__ float Wd[16][65];
    int t = threadIdx.x;
    int to = t >> 4, tn = t & 15;
    float accA[4][4] = {}, accC[4][4] = {};
    int C2 = 2 * C;
    for (int kk = 0; kk < C; kk += 16) {
        for (int i = t; i < 16 * 64; i += 256) {
            int k = i & 15, o = i >> 4;
            float wl = 0.f, wr = 0.f;
            if (kk + k < C) {
                wl = W[(size_t)(o0 + o) * C2 + kk + k];
                wr = W[(size_t)(o0 + o) * C2 + C + kk + k];
            }
            Wl[k][o] = wl; Wd[k][o] = wr - wl;
        }
        for (int i = t; i < 16 * 64; i += 256) {
            int k = i >> 6, n = i & 63;
            Xs[k][n] = (kk + k < C) ? X[(size_t)(kk + k) * NN + n0 + n] : 0.f;
        }
        __syncthreads();
        #pragma unroll
        for (int k = 0; k < 16; k++) {
            float wo[4], wd[4], xv[4];
            #pragma unroll
            for (int i = 0; i < 4; i++) {
                wo[i] = Wl[k][to * 4 + i]; wd[i] = Wd[k][to * 4 + i]; xv[i] = Xs[k][tn * 4 + i];
            }
            #pragma unroll
            for (int i = 0; i < 4; i++)
                #pragma unroll
                for (int j = 0; j < 4; j++) {
                    accA[i][j] += wo[i] * xv[j];
                    accC[i][j] += wd[i] * xv[j];
                }
        }
        __syncthreads();
    }
    #pragma unroll
    for (int i = 0; i < 4; i++) {
        int o = o0 + to * 4 + i;
        float4 a4, c4;
        #pragma unroll
        for (int j = 0; j < 4; j++) { (&a4.x)[j] = accA[i][j]; (&c4.x)[j] = accC[i][j]; }
        *reinterpret_cast<float4*>(&Aout[(size_t)o * NN + n0 + tn * 4]) = a4;
        *reinterpret_cast<float4*>(&Cout[(size_t)o * NN + n0 + tn * 4]) = c4;
    }
}

// ---------------- plain GEMM for w5 (512x512 @ xcat) -> y5 ----------------
__global__ __launch_bounds__(256) void gemm5_kernel(const float* __restrict__ W) {
    int b = blockIdx.z;
    const float* X = g_xcat + (size_t)b * 512 * NN;
    float* Y = g_y5 + (size_t)b * 512 * NN;
    int o0 = blockIdx.y * 64, n0 = blockIdx.x * 64;
    __shared__ float Xs[16][65];
    __shared__ float Ws[16][65];
    int t = threadIdx.x;
    int to = t >> 4, tn = t & 15;
    float acc[4][4] = {};
    for (int kk = 0; kk < 512; kk += 16) {
        for (int i = t; i < 16 * 64; i += 256) {
            int k = i & 15, o = i >> 4;
            Ws[k][o] = W[(size_t)(o0 + o) * 512 + kk + k];
        }
        for (int i = t; i < 16 * 64; i += 256) {
            int k = i >> 6, n = i & 63;
            Xs[k][n] = X[(size_t)(kk + k) * NN + n0 + n];
        }
        __syncthreads();
        #pragma unroll
        for (int k = 0; k < 16; k++) {
            float wo[4], xv[4];
            #pragma unroll
            for (int i = 0; i < 4; i++) { wo[i] = Ws[k][to * 4 + i]; xv[i] = Xs[k][tn * 4 + i]; }
            #pragma unroll
            for (int i = 0; i < 4; i++)
                #pragma unroll
                for (int j = 0; j < 4; j++)
                    acc[i][j] += wo[i] * xv[j];
        }
        __syncthreads();
    }
    #pragma unroll
    for (int i = 0; i < 4; i++) {
        int o = o0 + to * 4 + i;
        float4 a4;
        #pragma unroll
        for (int j = 0; j < 4; j++) (&a4.x)[j] = acc[i][j];
        *reinterpret_cast<float4*>(&Y[(size_t)o * NN + n0 + tn * 4]) = a4;
    }
}

// ---------------- zero BN accumulators ----------------
__global__ void zero_stats() {
    int t = blockIdx.x * 256 + threadIdx.x;
    if (t < 512) { g_sum[t] = 0.f; g_sumsq[t] = 0.f; }
}

// ---------------- BN stats for edge block (over b,n,k) ----------------
__global__ __launch_bounds__(128) void stats_edge(int O) {
    int b = blockIdx.z, o = blockIdx.y;
    int n = blockIdx.x * 128 + threadIdx.x;
    const float* Arow = g_A + ((size_t)b * O + o) * NN;
    float cv = g_Cc[((size_t)b * O + o) * NN + n];
    const int* ip = g_idx + ((size_t)b * NN + n) * KK;
    float s = 0.f, s2 = 0.f;
    #pragma unroll
    for (int k = 0; k < KK; k++) {
        float v = Arow[ip[k]] + cv;
        s += v; s2 += v * v;
    }
    __shared__ float ss[128], ss2[128];
    ss[threadIdx.x] = s; ss2[threadIdx.x] = s2;
    __syncthreads();
    for (int st = 64; st > 0; st >>= 1) {
        if (threadIdx.x < st) {
            ss[threadIdx.x] += ss[threadIdx.x + st];
            ss2[threadIdx.x] += ss2[threadIdx.x + st];
        }
        __syncthreads();
    }
    if (threadIdx.x == 0) { atomicAdd(&g_sum[o], ss[0]); atomicAdd(&g_sumsq[o], ss2[0]); }
}

// ---------------- finalize BN scale/shift ----------------
__global__ void finalize_bn(const float* __restrict__ gam, const float* __restrict__ bet,
                            float inv_cnt, int O) {
    int o = blockIdx.x * 256 + threadIdx.x;
    if (o >= O) return;
    float mean = g_sum[o] * inv_cnt;
    float var = g_sumsq[o] * inv_cnt - mean * mean;
    float sc = gam[o] * rsqrtf(var + 1e-5f);
    g_scale[o] = sc;
    g_shift[o] = bet[o] - mean * sc;
}

// ---------------- BN apply + leakyReLU + max over k -> xcat slice ----------------
__global__ __launch_bounds__(128) void apply_edge(int O, int coff) {
    int b = blockIdx.z, o = blockIdx.y;
    int n = blockIdx.x * 128 + threadIdx.x;
    const float* Arow = g_A + ((size_t)b * O + o) * NN;
    float cv = g_Cc[((size_t)b * O + o) * NN + n];
    const int* ip = g_idx + ((size_t)b * NN + n) * KK;
    float sc = g_scale[o], sh = g_shift[o];
    float m = -3.4e38f;
    #pragma unroll
    for (int k = 0; k < KK; k++) {
        float v = Arow[ip[k]] + cv;
        v = v * sc + sh;
        v = (v > 0.f) ? v : 0.2f * v;
        m = fmaxf(m, v);
    }
    g_xcat[((size_t)b * 512 + coff + o) * NN + n] = m;
}

// ---------------- BN stats for y5 (over b,n) ----------------
__global__ __launch_bounds__(256) void stats5() {
    int o = blockIdx.y;
    int i = blockIdx.x * 256 + threadIdx.x;     // b*NN + n
    int b = i >> 11, n = i & (NN - 1);
    float v = g_y5[((size_t)b * 512 + o) * NN + n];
    __shared__ float ss[256], ss2[256];
    ss[threadIdx.x] = v; ss2[threadIdx.x] = v * v;
    __syncthreads();
    for (int st = 128; st > 0; st >>= 1) {
        if (threadIdx.x < st) {
            ss[threadIdx.x] += ss[threadIdx.x + st];
            ss2[threadIdx.x] += ss2[threadIdx.x + st];
        }
        __syncthreads();
    }
    if (threadIdx.x == 0) { atomicAdd(&g_sum[o], ss[0]); atomicAdd(&g_sumsq[o], ss2[0]); }
}

// ---------------- BN apply + lrelu + max over n -> pooled + feat output ----------------
__global__ __launch_bounds__(256) void pool5(float* __restrict__ out) {
    int o = blockIdx.x, b = blockIdx.y;
    float sc = g_scale[o], sh = g_shift[o];
    const float* Y = g_y5 + ((size_t)b * 512 + o) * NN;
    float m = -3.4e38f;
    for (int n = threadIdx.x; n < NN; n += 256) {
        float v = Y[n] * sc + sh;
        v = (v > 0.f) ? v : 0.2f * v;
        m = fmaxf(m, v);
    }
    __shared__ float sm[256];
    sm[threadIdx.x] = m;
    __syncthreads();
    for (int st = 128; st > 0; st >>= 1) {
        if (threadIdx.x < st) sm[threadIdx.x] = fmaxf(sm[threadIdx.x], sm[threadIdx.x + st]);
        __syncthreads();
    }
    if (threadIdx.x == 0) {
        g_pooled[b * 512 + o] = sm[0];
        out[b * 512 + o] = sm[0];                 // feat (B,1,512)
    }
}

// ---------------- embedding + clustering ----------------
__global__ __launch_bounds__(256) void final_kernel(const float* __restrict__ w_emb,
                                                    const float* __restrict__ w_clu,
                                                    float* __restrict__ out) {
    __shared__ float sp[BB * 512];
    __shared__ float se[BB * 128];
    __shared__ float sq[BB * 10];
    __shared__ float ssum[BB];
    int t = threadIdx.x;
    for (int i = t; i < BB * 512; i += 256) sp[i] = g_pooled[i];
    __syncthreads();
    for (int i = t; i < BB * 128; i += 256) {
        int b = i >> 7, f = i & 127;
        float s = 0.f;
        for (int o = 0; o < 512; o++) s += sp[b * 512 + o] * w_emb[(size_t)f * 512 + o];
        se[i] = s;
        out[BB * 512 + i] = s;                    // embedding (B,128)
    }
    __syncthreads();
    if (t < 80) {
        int b = t / 10, c = t % 10;
        float d2 = 0.f;
        for (int f = 0; f < 128; f++) {
            float dd = se[b * 128 + f] - w_clu[c * 128 + f];
            d2 += dd * dd;
        }
        sq[t] = 1.0f / (1.0f + d2);               // alpha=1 -> power -1
    }
    __syncthreads();
    if (t < 8) {
        float s = 0.f;
        for (int c = 0; c < 10; c++) s += sq[t * 10 + c];
        ssum[t] = s;
    }
    __syncthreads();
    if (t < 80) out[BB * 512 + BB * 128 + t] = sq[t] / ssum[t / 10];
}

// ---------------- host launch ----------------
static void run_block(const float* Xsrc, int bstride, int Cin,
                      const float* W, const float* gam, const float* bet,
                      int O, int coff) {
    xx_kernel<<<BB * NN / 256, 256>>>(Xsrc, Cin, bstride);
    dim3 dg(NN / 64, NN / 64, BB);
    knn_dist_kernel<<<dg, 256>>>(Xsrc, Cin, bstride);
    topk_kernel<<<BB * NN, 256>>>();
    dim3 eg(NN / 64, O / 64, BB);
    edge_gemm_kernel<<<eg, 256>>>(W, Xsrc, Cin, O, bstride);
    zero_stats<<<2, 256>>>();
    dim3 sg(NN / 128, O, BB);
    stats_edge<<<sg, 128>>>(O);
    finalize_bn<<<(O + 255) / 256, 256>>>(gam, bet, 1.0f / (float)(BB * NN * KK), O);
    apply_edge<<<sg, 128>>>(O, coff);
}

extern "C" void kernel_launch(void* const* d_in, const int* in_sizes, int n_in,
                              void* d_out, int out_size) {
    const float* x     = (const float*)d_in[0];
    const float* w1    = (const float*)d_in[1];
    const float* g1    = (const float*)d_in[2];
    const float* b1    = (const float*)d_in[3];
    const float* w2    = (const float*)d_in[4];
    const float* g2    = (const float*)d_in[5];
    const float* b2    = (const float*)d_in[6];
    const float* w3    = (const float*)d_in[7];
    const float* g3    = (const float*)d_in[8];
    const float* b3    = (const float*)d_in[9];
    const float* w4    = (const float*)d_in[10];
    const float* g4    = (const float*)d_in[11];
    const float* b4    = (const float*)d_in[12];
    const float* w5    = (const float*)d_in[13];
    const float* g5    = (const float*)d_in[14];
    const float* b5    = (const float*)d_in[15];
    const float* wemb  = (const float*)d_in[16];
    const float* wclu  = (const float*)d_in[17];
    float* out = (float*)d_out;

    static float* p_xt = nullptr;
    static float* p_xcat = nullptr;
    if (!p_xt) {
        cudaGetSymbolAddress((void**)&p_xt, g_xt);
        cudaGetSymbolAddress((void**)&p_xcat, g_xcat);
    }

    xt_kernel<<<BB * NN / 256, 256>>>(x);

    run_block(p_xt,            3 * NN,   3,   w1, g1, b1,  64, 0);
    run_block(p_xcat,          512 * NN, 64,  w2, g2, b2,  64, 64);
    run_block(p_xcat + 64 * NN,  512 * NN, 64,  w3, g3, b3, 128, 128);
    run_block(p_xcat + 128 * NN, 512 * NN, 128, w4, g4, b4, 256, 256);

    dim3 gg5(NN / 64, 512 / 64, BB);
    gemm5_kernel<<<gg5, 256>>>(w5);
    zero_stats<<<2, 256>>>();
    stats5<<<dim3(BB * NN / 256, 512), 256>>>();
    finalize_bn<<<2, 256>>>(g5, b5, 1.0f / (float)(BB * NN), 512);
    pool5<<<dim3(512, BB), 256>>>(out);
    final_kernel<<<1, 256>>>(wemb, wclu, out);
}